// round 14
// baseline (speedup 1.0000x reference)
#include <cuda_runtime.h>

#define SEQ   96
#define PRED  16
#define HID   64
#define FEAT  7
#define BPB   4               // batches per block
#define NBLK  128             // 512/4 — one block per SM, single wave
#define NTHR  256
#define WIN   (SEQ + PRED)

typedef unsigned long long ull;

// Precomputed bias-included input projections for the 96 original window slots:
// XG[s][blk][thr] = (biasA + rowA·x_bE, biasA + rowA·x_bO,
//                    biasB + rowB·x_bE, biasB + rowB·x_bO)
// matching the main kernel's per-thread (bp, gp, u) mapping. 50.3 MB — L2-resident.
__device__ float4 XG[SEQ * NBLK * NTHR];

static __device__ __forceinline__ ull pack2(float a, float b){
    ull r; asm("mov.b64 %0, {%1, %2};" : "=l"(r) : "f"(a), "f"(b)); return r;
}
static __device__ __forceinline__ void unpack2(ull v, float &a, float &b){
    asm("mov.b64 {%0, %1}, %2;" : "=f"(a), "=f"(b) : "l"(v));
}
// d = a*b + d, packed f32x2 (Blackwell FFMA2), exact fp32 per lane
static __device__ __forceinline__ void ffma2(ull &d, ull a, ull b){
    asm("fma.rn.f32x2 %0, %1, %2, %0;" : "+l"(d) : "l"(a), "l"(b));
}

static __device__ __forceinline__ float sigmoid_fast(float x){
    float e = __expf(-x);
    return __fdividef(1.0f, 1.0f + e);
}
static __device__ __forceinline__ float tanhf_fast(float x){
    float e = __expf(-2.0f * x);
    return __fdividef(2.0f, 1.0f + e) - 1.0f;
}

// ---------------- one-shot xg precompute: grid (NBLK, SEQ) x 256 ----------------
__global__ void __launch_bounds__(NTHR)
xg_kernel(const float* __restrict__ x, const float* __restrict__ W_ih,
          const float* __restrict__ b_ih, const float* __restrict__ b_hh)
{
    const int s   = blockIdx.y;
    const int blk = blockIdx.x;
    const int thr = threadIdx.x;
    const int bp  = thr >> 7;
    const int gp  = thr & 1;
    const int u   = (thr >> 1) & 63;
    const int rA  = gp * 128 + u;
    const int rB  = rA + 64;
    const int bE  = blk * BPB + 2 * bp;

    const float* xe = x + ((size_t)bE       * SEQ + s) * FEAT;
    const float* xo = x + ((size_t)(bE + 1) * SEQ + s) * FEAT;
    // bias-included, same fmaf order as the in-kernel path
    float a0 = b_ih[rA] + b_hh[rA];
    float a1 = a0;
    float c0 = b_ih[rB] + b_hh[rB];
    float c1 = c0;
    #pragma unroll
    for (int f = 0; f < FEAT; f++){
        float wa = W_ih[rA * FEAT + f];
        float wb = W_ih[rB * FEAT + f];
        float xev = xe[f], xov = xo[f];
        a0 = fmaf(wa, xev, a0);
        a1 = fmaf(wa, xov, a1);
        c0 = fmaf(wb, xev, c0);
        c1 = fmaf(wb, xov, c1);
    }
    XG[((size_t)s * NBLK + blk) * NTHR + thr] = make_float4(a0, a1, c0, c1);
}

__global__ void __launch_bounds__(NTHR, 1)
lstm_ar_kernel(const float* __restrict__ x,
               const float* __restrict__ W_ih,
               const float* __restrict__ W_hh,
               const float* __restrict__ b_ih,
               const float* __restrict__ b_hh,
               const float* __restrict__ fc_W,
               const float* __restrict__ fc_b,
               float* __restrict__ out)
{
    // sliding input window: [t][feat][b] — only appended slots (>=SEQ) read for x-proj
    __shared__ float sh_xw[WIN * FEAT * BPB];
    // hidden state, double-buffered, batch-major: [buf][b][u]
    __shared__ float h_sh[2][BPB][HID];
    __shared__ float sh_fcW[FEAT * HID];
    __shared__ float sh_fcb[FEAT];

    const int tid = threadIdx.x;            // 0..255
    const int bp  = tid >> 7;               // batch pair (warp-aligned half)
    const int gp  = tid & 1;                // 0: rows i,f   1: rows g,o
    const int u   = (tid >> 1) & 63;        // hidden unit
    const int rA  = gp * 128 + u;           // i-row (gp0) / g-row (gp1)
    const int rB  = gp * 128 + 64 + u;      // f-row (gp0) / o-row (gp1)
    const int bO  = 2 * bp + gp;            // batch whose cell state this thread owns
    const int b0  = blockIdx.x * BPB;
    const int barid = 1 + bp;               // named barrier per independent half
    const int tl  = tid & 127;              // index within half

    const float4* xg_base = &XG[(size_t)blockIdx.x * NTHR + tid];
    const size_t  xstride = (size_t)NBLK * NTHR;   // float4s per slot

    // ---------------- one-time init ----------------
    for (int i = tid; i < SEQ * FEAT * BPB; i += NTHR){
        int b = i & 3;
        int q = i >> 2;
        int f = q % FEAT;
        int t = q / FEAT;
        sh_xw[(t * FEAT + f) * BPB + b] =
            x[(size_t)(b0 + b) * SEQ * FEAT + t * FEAT + f];
    }
    for (int i = tid; i < FEAT * HID; i += NTHR) sh_fcW[i] = fc_W[i];
    if (tid < FEAT) sh_fcb[tid] = fc_b[tid];
    {
        float* hz = &h_sh[0][0][0];
        for (int i = tid; i < 2 * BPB * HID; i += NTHR) hz[i] = 0.0f;
    }

    // W_hh rows rA, rB as natural column-pairs: 64 u64 = 128 regs
    ull whhA[HID / 2], whhB[HID / 2];
    {
        const ull* wa = reinterpret_cast<const ull*>(W_hh + (size_t)rA * HID);
        const ull* wb = reinterpret_cast<const ull*>(W_hh + (size_t)rB * HID);
        #pragma unroll
        for (int c = 0; c < HID / 2; c++){ whhA[c] = wa[c]; whhB[c] = wb[c]; }
    }
    // W_ih rows, splatted — used only for appended slots (s >= SEQ)
    ull wihA2[FEAT], wihB2[FEAT];
    #pragma unroll
    for (int f = 0; f < FEAT; f++){
        float wa = W_ih[rA * FEAT + f];
        float wb = W_ih[rB * FEAT + f];
        wihA2[f] = pack2(wa, wa);
        wihB2[f] = pack2(wb, wb);
    }
    const float biasA = b_ih[rA] + b_hh[rA];
    const float biasB = b_ih[rB] + b_hh[rB];
    const ull biasA2 = pack2(biasA, biasA);
    const ull biasB2 = pack2(biasB, biasB);

    float c_reg = 0.0f;        // cell state of (batch bO, unit u)
    int p = 0;

    __syncthreads();           // only global sync: after init

    // ------- 16 AR iterations x 96 steps; the two halves never re-couple -------
    for (int k = 0; k < PRED; k++){
        // x-projection for t=0 (slot k < SEQ always): precomputed, bias included
        const float4* xp = xg_base + (size_t)k * xstride;
        float4 xg = __ldg(xp);

        for (int t = 0; t < SEQ; t++){
            // ---- h-dot: accumulators seeded with prefetched (bias + x-proj) ----
            ull aA0 = pack2(xg.x, 0.0f), aA1 = pack2(xg.y, 0.0f);
            ull aB0 = pack2(xg.z, 0.0f), aB1 = pack2(xg.w, 0.0f);
            const ulonglong2* hE =
                reinterpret_cast<const ulonglong2*>(&h_sh[p][2*bp    ][0]);
            const ulonglong2* hO =
                reinterpret_cast<const ulonglong2*>(&h_sh[p][2*bp + 1][0]);
            #pragma unroll
            for (int c = 0; c < 16; c++){
                ulonglong2 u0 = hE[c];          // cols 4c..4c+3, batch even (broadcast)
                ulonglong2 u1 = hO[c];          // batch odd
                ffma2(aA0, u0.x, whhA[2*c]);
                ffma2(aB0, u0.x, whhB[2*c]);
                ffma2(aA0, u0.y, whhA[2*c+1]);
                ffma2(aB0, u0.y, whhB[2*c+1]);
                ffma2(aA1, u1.x, whhA[2*c]);
                ffma2(aB1, u1.x, whhB[2*c]);
                ffma2(aA1, u1.y, whhA[2*c+1]);
                ffma2(aB1, u1.y, whhB[2*c+1]);
            }
            float e, o;
            float vA0, vA1, vB0, vB1;
            unpack2(aA0, e, o); vA0 = e + o;   // rowA, batch even
            unpack2(aA1, e, o); vA1 = e + o;   // rowA, batch odd
            unpack2(aB0, e, o); vB0 = e + o;   // rowB, batch even
            unpack2(aB1, e, o); vB1 = e + o;   // rowB, batch odd

            // ---- pair exchange: 2 shfl.xor with lane^1 (gp partner) ----
            // gp0 owns batch even -> needs (g,o) even; sends (i,f) odd.
            // gp1 owns batch odd  -> needs (i,f) odd;  sends (g,o) even.
            float sA = gp ? vA0 : vA1;
            float sB = gp ? vB0 : vB1;
            float rAv = __shfl_xor_sync(0xffffffffu, sA, 1);
            float rBv = __shfl_xor_sync(0xffffffffu, sB, 1);
            float pi = gp ? rAv : vA0;
            float pf = gp ? rBv : vB0;
            float pg = gp ? vA1 : rAv;
            float po = gp ? vB1 : rBv;

            // ---- activations + cell update for (bO, u) ----
            float gi = sigmoid_fast(pi);
            float gf = sigmoid_fast(pf);
            float gg = tanhf_fast(pg);
            float go = sigmoid_fast(po);
            c_reg = fmaf(gf, c_reg, gi * gg);
            h_sh[p ^ 1][bO][u] = go * tanhf_fast(c_reg);

            // ---- prefetch next step's x-projection INSIDE the barrier shadow ----
            if (t < SEQ - 1){
                const int sn = k + t + 1;
                xp += xstride;
                if (sn < SEQ){
                    xg = __ldg(xp);            // precomputed slot (L2 hit, ~250cyc slack)
                } else {
                    // appended-prediction slot: on-the-fly (window stable within k)
                    ull xA = biasA2, xB = biasB2;
                    const float* xrow = &sh_xw[sn * FEAT * BPB + 2 * bp];
                    #pragma unroll
                    for (int f = 0; f < FEAT; f++){
                        ull xx = *reinterpret_cast<const ull*>(xrow + f * BPB);
                        ffma2(xA, xx, wihA2[f]);
                        ffma2(xB, xx, wihB2[f]);
                    }
                    float q0, q1, q2, q3;
                    unpack2(xA, q0, q1);
                    unpack2(xB, q2, q3);
                    xg = make_float4(q0, q1, q2, q3);
                }
            }

            asm volatile("bar.sync %0, 128;" :: "r"(barid) : "memory");
            p ^= 1;
        }

        // ---- per-half fc head: this half's 2 batches only ----
        if (tl < FEAT * 2){
            int bl = tl / FEAT;                // 0..1 within the half
            int o2 = tl - bl * FEAT;
            int b  = 2 * bp + bl;
            float acc = sh_fcb[o2];
            #pragma unroll
            for (int jj = 0; jj < HID; jj++)
                acc += h_sh[p][b][jj] * sh_fcW[o2 * HID + jj];
            out[(size_t)(b0 + b) * PRED * FEAT + k * FEAT + o2] = acc;
            sh_xw[((SEQ + k) * FEAT + o2) * BPB + b] = acc;
        }
        asm volatile("bar.sync %0, 128;" :: "r"(barid) : "memory");
    }
}

extern "C" void kernel_launch(void* const* d_in, const int* in_sizes, int n_in,
                              void* d_out, int out_size)
{
    const float* x    = (const float*)d_in[0];
    const float* W_ih = (const float*)d_in[1];
    const float* W_hh = (const float*)d_in[2];
    const float* b_ih = (const float*)d_in[3];
    const float* b_hh = (const float*)d_in[4];
    const float* fc_W = (const float*)d_in[5];
    const float* fc_b = (const float*)d_in[6];
    float* out = (float*)d_out;

    xg_kernel<<<dim3(NBLK, SEQ), NTHR>>>(x, W_ih, b_ih, b_hh);
    lstm_ar_kernel<<<NBLK, NTHR>>>(x, W_ih, W_hh, b_ih, b_hh, fc_W, fc_b, out);
}

// round 15
// speedup vs baseline: 1.1355x; 1.1355x over previous
#include <cuda_runtime.h>

#define SEQ   96
#define PRED  16
#define HID   64
#define FEAT  7
#define BPB   4               // batches per block
#define NBLK  128             // 512/4 — one block per SM, single wave
#define NTHR  256
#define WIN   (SEQ + PRED)

typedef unsigned long long ull;

// Precomputed bias-included input projections for the 96 original window slots:
// XG[s][blk][thr] = (biasA + rowA·x_bE, biasA + rowA·x_bO,
//                    biasB + rowB·x_bE, biasB + rowB·x_bO)
// 50.3 MB — L2-resident after first sweep.
__device__ float4 XG[SEQ * NBLK * NTHR];

static __device__ __forceinline__ ull pack2(float a, float b){
    ull r; asm("mov.b64 %0, {%1, %2};" : "=l"(r) : "f"(a), "f"(b)); return r;
}
static __device__ __forceinline__ void unpack2(ull v, float &a, float &b){
    asm("mov.b64 {%0, %1}, %2;" : "=f"(a), "=f"(b) : "l"(v));
}
// d = a*b + d, packed f32x2 (Blackwell FFMA2), exact fp32 per lane
static __device__ __forceinline__ void ffma2(ull &d, ull a, ull b){
    asm("fma.rn.f32x2 %0, %1, %2, %0;" : "+l"(d) : "l"(a), "l"(b));
}

static __device__ __forceinline__ float sigmoid_fast(float x){
    float e = __expf(-x);
    return __fdividef(1.0f, 1.0f + e);
}
static __device__ __forceinline__ float tanhf_fast(float x){
    float e = __expf(-2.0f * x);
    return __fdividef(2.0f, 1.0f + e) - 1.0f;
}

// ---------------- one-shot xg precompute: grid (NBLK, SEQ) x 256 ----------------
__global__ void __launch_bounds__(NTHR)
xg_kernel(const float* __restrict__ x, const float* __restrict__ W_ih,
          const float* __restrict__ b_ih, const float* __restrict__ b_hh)
{
    const int s   = blockIdx.y;
    const int blk = blockIdx.x;
    const int thr = threadIdx.x;
    const int bp  = thr >> 7;
    const int gp  = thr & 1;
    const int u   = (thr >> 1) & 63;
    const int rA  = gp * 128 + u;
    const int rB  = rA + 64;
    const int bE  = blk * BPB + 2 * bp;

    const float* xe = x + ((size_t)bE       * SEQ + s) * FEAT;
    const float* xo = x + ((size_t)(bE + 1) * SEQ + s) * FEAT;
    float a0 = b_ih[rA] + b_hh[rA];
    float a1 = a0;
    float c0 = b_ih[rB] + b_hh[rB];
    float c1 = c0;
    #pragma unroll
    for (int f = 0; f < FEAT; f++){
        float wa = W_ih[rA * FEAT + f];
        float wb = W_ih[rB * FEAT + f];
        float xev = xe[f], xov = xo[f];
        a0 = fmaf(wa, xev, a0);
        a1 = fmaf(wa, xov, a1);
        c0 = fmaf(wb, xev, c0);
        c1 = fmaf(wb, xov, c1);
    }
    XG[((size_t)s * NBLK + blk) * NTHR + thr] = make_float4(a0, a1, c0, c1);
}

__global__ void __launch_bounds__(NTHR, 1)
lstm_ar_kernel(const float* __restrict__ x,
               const float* __restrict__ W_ih,
               const float* __restrict__ W_hh,
               const float* __restrict__ b_ih,
               const float* __restrict__ b_hh,
               const float* __restrict__ fc_W,
               const float* __restrict__ fc_b,
               float* __restrict__ out)
{
    // sliding input window: [t][feat][b] — only appended slots (>=SEQ) read for x-proj
    __shared__ float sh_xw[WIN * FEAT * BPB];
    // hidden state, double-buffered, batch-major: [buf][b][u]
    __shared__ float h_sh[2][BPB][HID];
    __shared__ float sh_fcW[FEAT * HID];
    __shared__ float sh_fcb[FEAT];

    const int tid = threadIdx.x;            // 0..255
    const int bp  = tid >> 7;               // batch pair (warp-aligned half)
    const int gp  = tid & 1;                // 0: rows i,f   1: rows g,o
    const int u   = (tid >> 1) & 63;        // hidden unit
    const int rA  = gp * 128 + u;           // i-row (gp0) / g-row (gp1)
    const int rB  = gp * 128 + 64 + u;      // f-row (gp0) / o-row (gp1)
    const int bO  = 2 * bp + gp;            // batch whose cell state this thread owns
    const int b0  = blockIdx.x * BPB;
    const int barid = 1 + bp;               // named barrier per independent half
    const int tl  = tid & 127;              // index within half

    // per-thread XG column base; slot s is at byte offset s<<19 (32768 float4/slot)
    const char* xg_base =
        reinterpret_cast<const char*>(&XG[(size_t)blockIdx.x * NTHR + tid]);

    // ---------------- one-time init ----------------
    for (int i = tid; i < SEQ * FEAT * BPB; i += NTHR){
        int b = i & 3;
        int q = i >> 2;
        int f = q % FEAT;
        int t = q / FEAT;
        sh_xw[(t * FEAT + f) * BPB + b] =
            x[(size_t)(b0 + b) * SEQ * FEAT + t * FEAT + f];
    }
    for (int i = tid; i < FEAT * HID; i += NTHR) sh_fcW[i] = fc_W[i];
    if (tid < FEAT) sh_fcb[tid] = fc_b[tid];
    {
        float* hz = &h_sh[0][0][0];
        for (int i = tid; i < 2 * BPB * HID; i += NTHR) hz[i] = 0.0f;
    }

    // W_hh rows rA, rB as natural column-pairs: 64 u64 = 128 regs
    ull whhA[HID / 2], whhB[HID / 2];
    {
        const ull* wa = reinterpret_cast<const ull*>(W_hh + (size_t)rA * HID);
        const ull* wb = reinterpret_cast<const ull*>(W_hh + (size_t)rB * HID);
        #pragma unroll
        for (int c = 0; c < HID / 2; c++){ whhA[c] = wa[c]; whhB[c] = wb[c]; }
    }
    // W_ih rows, splatted — used only for appended slots (s >= SEQ)
    ull wihA2[FEAT], wihB2[FEAT];
    #pragma unroll
    for (int f = 0; f < FEAT; f++){
        float wa = W_ih[rA * FEAT + f];
        float wb = W_ih[rB * FEAT + f];
        wihA2[f] = pack2(wa, wa);
        wihB2[f] = pack2(wb, wb);
    }
    const float biasA = b_ih[rA] + b_hh[rA];
    const float biasB = b_ih[rB] + b_hh[rB];
    const ull biasA2 = pack2(biasA, biasA);
    const ull biasB2 = pack2(biasB, biasB);

    float c_reg = 0.0f;        // cell state of (batch bO, unit u)
    int p = 0;

    __syncthreads();           // only global sync: after init

    // initial xg for (k=0, t=0) = slot 0 (precomputed)
    float4 xg = __ldg(reinterpret_cast<const float4*>(xg_base));

    // ------- 16 AR iterations x 96 steps; the two halves never re-couple -------
    for (int k = 0; k < PRED; k++){
        for (int t = 0; t < SEQ; t++){
            // ---- top-of-step: prefetch NEXT slot's xg (full h-dot of slack) ----
            // next slot: k+t+1 within this iteration; k+1 when wrapping to next k
            const int sn = (t == SEQ - 1) ? (k + 1) : (k + t + 1);
            float4 xg_nxt;
            bool nxt_ldg = (sn < SEQ);
            if (nxt_ldg){
                xg_nxt = __ldg(reinterpret_cast<const float4*>(
                    xg_base + ((size_t)sn << 19)));
            } else {
                // appended-prediction slot: on-the-fly (window stable within k)
                ull xA = biasA2, xB = biasB2;
                const float* xrow = &sh_xw[sn * FEAT * BPB + 2 * bp];
                #pragma unroll
                for (int f = 0; f < FEAT; f++){
                    ull xx = *reinterpret_cast<const ull*>(xrow + f * BPB);
                    ffma2(xA, xx, wihA2[f]);
                    ffma2(xB, xx, wihB2[f]);
                }
                float q0, q1, q2, q3;
                unpack2(xA, q0, q1);
                unpack2(xB, q2, q3);
                xg_nxt = make_float4(q0, q1, q2, q3);
            }

            // ---- h-dot: accumulators seeded with current (bias + x-proj) ----
            ull aA0 = pack2(xg.x, 0.0f), aA1 = pack2(xg.y, 0.0f);
            ull aB0 = pack2(xg.z, 0.0f), aB1 = pack2(xg.w, 0.0f);
            const ulonglong2* hE =
                reinterpret_cast<const ulonglong2*>(&h_sh[p][2*bp    ][0]);
            const ulonglong2* hO =
                reinterpret_cast<const ulonglong2*>(&h_sh[p][2*bp + 1][0]);
            #pragma unroll
            for (int c = 0; c < 16; c++){
                ulonglong2 u0 = hE[c];          // cols 4c..4c+3, batch even (broadcast)
                ulonglong2 u1 = hO[c];          // batch odd
                ffma2(aA0, u0.x, whhA[2*c]);
                ffma2(aB0, u0.x, whhB[2*c]);
                ffma2(aA0, u0.y, whhA[2*c+1]);
                ffma2(aB0, u0.y, whhB[2*c+1]);
                ffma2(aA1, u1.x, whhA[2*c]);
                ffma2(aB1, u1.x, whhB[2*c]);
                ffma2(aA1, u1.y, whhA[2*c+1]);
                ffma2(aB1, u1.y, whhB[2*c+1]);
            }
            float e, o;
            float vA0, vA1, vB0, vB1;
            unpack2(aA0, e, o); vA0 = e + o;   // rowA, batch even
            unpack2(aA1, e, o); vA1 = e + o;   // rowA, batch odd
            unpack2(aB0, e, o); vB0 = e + o;   // rowB, batch even
            unpack2(aB1, e, o); vB1 = e + o;   // rowB, batch odd

            // ---- pair exchange: 2 shfl.xor with lane^1 (gp partner) ----
            // gp0 owns batch even -> needs (g,o) even; sends (i,f) odd.
            // gp1 owns batch odd  -> needs (i,f) odd;  sends (g,o) even.
            float sA = gp ? vA0 : vA1;
            float sB = gp ? vB0 : vB1;
            float rAv = __shfl_xor_sync(0xffffffffu, sA, 1);
            float rBv = __shfl_xor_sync(0xffffffffu, sB, 1);
            float pi = gp ? rAv : vA0;
            float pf = gp ? rBv : vB0;
            float pg = gp ? vA1 : rAv;
            float po = gp ? vB1 : rBv;

            // ---- activations + cell update for (bO, u) ----
            float gi = sigmoid_fast(pi);
            float gf = sigmoid_fast(pf);
            float gg = tanhf_fast(pg);
            float go = sigmoid_fast(po);
            c_reg = fmaf(gf, c_reg, gi * gg);
            h_sh[p ^ 1][bO][u] = go * tanhf_fast(c_reg);

            // consume the prefetch (scoreboard wait lands here, ~full step of slack)
            xg = xg_nxt;

            asm volatile("bar.sync %0, 128;" :: "r"(barid) : "memory");
            p ^= 1;
        }

        // ---- per-half fc head: this half's 2 batches only ----
        if (tl < FEAT * 2){
            int bl = tl / FEAT;                // 0..1 within the half
            int o2 = tl - bl * FEAT;
            int b  = 2 * bp + bl;
            float acc = sh_fcb[o2];
            #pragma unroll
            for (int jj = 0; jj < HID; jj++)
                acc += h_sh[p][b][jj] * sh_fcW[o2 * HID + jj];
            out[(size_t)(b0 + b) * PRED * FEAT + k * FEAT + o2] = acc;
            sh_xw[((SEQ + k) * FEAT + o2) * BPB + b] = acc;
        }
        asm volatile("bar.sync %0, 128;" :: "r"(barid) : "memory");
    }
}

extern "C" void kernel_launch(void* const* d_in, const int* in_sizes, int n_in,
                              void* d_out, int out_size)
{
    const float* x    = (const float*)d_in[0];
    const float* W_ih = (const float*)d_in[1];
    const float* W_hh = (const float*)d_in[2];
    const float* b_ih = (const float*)d_in[3];
    const float* b_hh = (const float*)d_in[4];
    const float* fc_W = (const float*)d_in[5];
    const float* fc_b = (const float*)d_in[6];
    float* out = (float*)d_out;

    xg_kernel<<<dim3(NBLK, SEQ), NTHR>>>(x, W_ih, b_ih, b_hh);
    lstm_ar_kernel<<<NBLK, NTHR>>>(x, W_ih, W_hh, b_ih, b_hh, fc_W, fc_b, out);
}

// round 16
// speedup vs baseline: 1.2165x; 1.0713x over previous
#include <cuda_runtime.h>

#define SEQ   96
#define PRED  16
#define HID   64
#define FEAT  7
#define BPB   4               // batches per block
#define NBLK  128             // 512/4 — one block per SM, single wave
#define NTHR  256
#define WIN   (SEQ + PRED)

typedef unsigned long long ull;

static __device__ __forceinline__ ull pack2(float a, float b){
    ull r; asm("mov.b64 %0, {%1, %2};" : "=l"(r) : "f"(a), "f"(b)); return r;
}
static __device__ __forceinline__ void unpack2(ull v, float &a, float &b){
    asm("mov.b64 {%0, %1}, %2;" : "=f"(a), "=f"(b) : "l"(v));
}
// d = a*b + d, packed f32x2 (Blackwell FFMA2), exact fp32 per lane
static __device__ __forceinline__ void ffma2(ull &d, ull a, ull b){
    asm("fma.rn.f32x2 %0, %1, %2, %0;" : "+l"(d) : "l"(a), "l"(b));
}

static __device__ __forceinline__ float sigmoid_fast(float x){
    float e = __expf(-x);
    return __fdividef(1.0f, 1.0f + e);
}
static __device__ __forceinline__ float tanhf_fast(float x){
    float e = __expf(-2.0f * x);
    return __fdividef(2.0f, 1.0f + e) - 1.0f;
}

__global__ void __launch_bounds__(NTHR, 1)
lstm_ar_kernel(const float* __restrict__ x,
               const float* __restrict__ W_ih,
               const float* __restrict__ W_hh,
               const float* __restrict__ b_ih,
               const float* __restrict__ b_hh,
               const float* __restrict__ fc_W,
               const float* __restrict__ fc_b,
               float* __restrict__ out)
{
    // sliding input window: [t][feat][b], b in [0,4)
    __shared__ float sh_xw[WIN * FEAT * BPB];
    // hidden state, double-buffered, batch-major: [buf][b][u]
    __shared__ float h_sh[2][BPB][HID];
    __shared__ float sh_fcW[FEAT * HID];
    __shared__ float sh_fcb[FEAT];

    const int tid = threadIdx.x;            // 0..255
    const int bp  = tid >> 7;               // batch pair (warp-aligned half)
    const int gp  = tid & 1;                // 0: rows i,f   1: rows g,o
    const int u   = (tid >> 1) & 63;        // hidden unit
    const int rA  = gp * 128 + u;           // i-row (gp0) / g-row (gp1)
    const int rB  = gp * 128 + 64 + u;      // f-row (gp0) / o-row (gp1)
    const int bO  = 2 * bp + gp;            // batch whose cell state this thread owns
    const int b0  = blockIdx.x * BPB;
    const int barid = 1 + bp;               // named barrier per independent half
    const int tl  = tid & 127;              // index within half

    // ---------------- one-time init ----------------
    for (int i = tid; i < SEQ * FEAT * BPB; i += NTHR){
        int b = i & 3;
        int q = i >> 2;
        int f = q % FEAT;
        int t = q / FEAT;
        sh_xw[(t * FEAT + f) * BPB + b] =
            x[(size_t)(b0 + b) * SEQ * FEAT + t * FEAT + f];
    }
    for (int i = tid; i < FEAT * HID; i += NTHR) sh_fcW[i] = fc_W[i];
    if (tid < FEAT) sh_fcb[tid] = fc_b[tid];
    {
        float* hz = &h_sh[0][0][0];
        for (int i = tid; i < 2 * BPB * HID; i += NTHR) hz[i] = 0.0f;
    }

    // W_hh rows rA, rB as natural column-pairs: 64 u64 = 128 regs
    ull whhA[HID / 2], whhB[HID / 2];
    {
        const ull* wa = reinterpret_cast<const ull*>(W_hh + (size_t)rA * HID);
        const ull* wb = reinterpret_cast<const ull*>(W_hh + (size_t)rB * HID);
        #pragma unroll
        for (int c = 0; c < HID / 2; c++){ whhA[c] = wa[c]; whhB[c] = wb[c]; }
    }
    // W_ih rows, splatted for batch-pair f32x2 x-projection
    ull wihA2[FEAT], wihB2[FEAT];
    #pragma unroll
    for (int f = 0; f < FEAT; f++){
        float wa = W_ih[rA * FEAT + f];
        float wb = W_ih[rB * FEAT + f];
        wihA2[f] = pack2(wa, wa);
        wihB2[f] = pack2(wb, wb);
    }
    const float biasA = b_ih[rA] + b_hh[rA];
    const float biasB = b_ih[rB] + b_hh[rB];
    const ull biasA2 = pack2(biasA, biasA);
    const ull biasB2 = pack2(biasB, biasB);

    float c_reg = 0.0f;        // cell state of (batch bO, unit u)
    int p = 0;

    __syncthreads();           // only global sync: after init

    // ------- 16 AR iterations x 96 steps; the two halves never re-couple -------
    for (int k = 0; k < PRED; k++){
        // prefetch x-projection for step t=0 (slot k; always an original slot)
        ull xA = biasA2, xB = biasB2;
        {
            const float* xrow = &sh_xw[k * FEAT * BPB + 2 * bp];
            #pragma unroll
            for (int f = 0; f < FEAT; f++){
                ull xx = *reinterpret_cast<const ull*>(xrow + f * BPB);
                ffma2(xA, xx, wihA2[f]);
                ffma2(xB, xx, wihB2[f]);
            }
        }

        for (int t = 0; t < SEQ; t++){
            // ---- consume prefetched x-projection (bias already included) ----
            float xa0, xa1, xb0, xb1;
            unpack2(xA, xa0, xa1);
            unpack2(xB, xb0, xb1);

            // ---- h-dot: accumulators seeded with (bias + x-proj) via MOV packs ----
            ull aA0 = pack2(xa0, 0.0f), aA1 = pack2(xa1, 0.0f);
            ull aB0 = pack2(xb0, 0.0f), aB1 = pack2(xb1, 0.0f);
            const ulonglong2* hE =
                reinterpret_cast<const ulonglong2*>(&h_sh[p][2*bp    ][0]);
            const ulonglong2* hO =
                reinterpret_cast<const ulonglong2*>(&h_sh[p][2*bp + 1][0]);
            #pragma unroll
            for (int c = 0; c < 16; c++){
                ulonglong2 u0 = hE[c];          // cols 4c..4c+3, batch even (broadcast)
                ulonglong2 u1 = hO[c];          // batch odd
                ffma2(aA0, u0.x, whhA[2*c]);
                ffma2(aB0, u0.x, whhB[2*c]);
                ffma2(aA0, u0.y, whhA[2*c+1]);
                ffma2(aB0, u0.y, whhB[2*c+1]);
                ffma2(aA1, u1.x, whhA[2*c]);
                ffma2(aB1, u1.x, whhB[2*c]);
                ffma2(aA1, u1.y, whhA[2*c+1]);
                ffma2(aB1, u1.y, whhB[2*c+1]);
            }
            float e, o;
            float vA0, vA1, vB0, vB1;
            unpack2(aA0, e, o); vA0 = e + o;   // rowA, batch even
            unpack2(aA1, e, o); vA1 = e + o;   // rowA, batch odd
            unpack2(aB0, e, o); vB0 = e + o;   // rowB, batch even
            unpack2(aB1, e, o); vB1 = e + o;   // rowB, batch odd

            // ---- pair exchange: 2 shfl.xor with lane^1 (gp partner) ----
            // gp0 owns batch even -> needs (g,o) even; sends (i,f) odd.
            // gp1 owns batch odd  -> needs (i,f) odd;  sends (g,o) even.
            float sA = gp ? vA0 : vA1;
            float sB = gp ? vB0 : vB1;
            float rAv = __shfl_xor_sync(0xffffffffu, sA, 1);
            float rBv = __shfl_xor_sync(0xffffffffu, sB, 1);
            float pi = gp ? rAv : vA0;
            float pf = gp ? rBv : vB0;
            float pg = gp ? vA1 : rAv;
            float po = gp ? vB1 : rBv;

            // ---- activations + cell update for (bO, u) ----
            float gi = sigmoid_fast(pi);
            float gf = sigmoid_fast(pf);
            float gg = tanhf_fast(pg);
            float go = sigmoid_fast(po);
            c_reg = fmaf(gf, c_reg, gi * gg);
            h_sh[p ^ 1][bO][u] = go * tanhf_fast(c_reg);

            // ---- split barrier: arrive now, overlap prefetch, sync later ----
            asm volatile("bar.arrive %0, 256;" :: "r"(barid) : "memory");

            // prefetch next step's x-projection inside the barrier-drain shadow
            // (window slots read here are stable for the whole k-iteration)
            if (t < SEQ - 1){
                xA = biasA2; xB = biasB2;
                const float* xrow = &sh_xw[(k + t + 1) * FEAT * BPB + 2 * bp];
                #pragma unroll
                for (int f = 0; f < FEAT; f++){
                    ull xx = *reinterpret_cast<const ull*>(xrow + f * BPB);
                    ffma2(xA, xx, wihA2[f]);
                    ffma2(xB, xx, wihB2[f]);
                }
            }

            asm volatile("bar.sync %0, 256;" :: "r"(barid) : "memory");
            p ^= 1;
        }

        // ---- per-half fc head: this half's 2 batches only ----
        if (tl < FEAT * 2){
            int bl = tl / FEAT;                // 0..1 within the half
            int o2 = tl - bl * FEAT;
            int b  = 2 * bp + bl;
            float acc = sh_fcb[o2];
            #pragma unroll
            for (int jj = 0; jj < HID; jj++)
                acc += h_sh[p][b][jj] * sh_fcW[o2 * HID + jj];
            out[(size_t)(b0 + b) * PRED * FEAT + k * FEAT + o2] = acc;
            sh_xw[((SEQ + k) * FEAT + o2) * BPB + b] = acc;
        }
        asm volatile("bar.sync %0, 128;" :: "r"(barid) : "memory");
    }
}

extern "C" void kernel_launch(void* const* d_in, const int* in_sizes, int n_in,
                              void* d_out, int out_size)
{
    const float* x    = (const float*)d_in[0];
    const float* W_ih = (const float*)d_in[1];
    const float* W_hh = (const float*)d_in[2];
    const float* b_ih = (const float*)d_in[3];
    const float* b_hh = (const float*)d_in[4];
    const float* fc_W = (const float*)d_in[5];
    const float* fc_b = (const float*)d_in[6];
    float* out = (float*)d_out;

    lstm_ar_kernel<<<NBLK, NTHR>>>(x, W_ih, W_hh, b_ih, b_hh, fc_W, fc_b, out);
}